// round 4
// baseline (speedup 1.0000x reference)
#include <cuda_runtime.h>
#include <cuda_bf16.h>

// ApproxNDCGLoss via histogram convolution, 3 launches.
//
//  rank_j = 1 + sum_i sigmoid(s_j - s_i)
//         ~ 1 + sum_g [ H_g*sig(x) - S1_g*sig'(x) ],  x = s_j - c_g
//  With t = tanh(x/2):  sig = 0.5+0.5t, sig' = 0.25(1-t^2), so per-bin
//  contribution = (0.5H - 0.25S1) + 0.5H*t + 0.25S1*t^2 = a0 + a1*t + a2*t^2,
//  where sum_g a0 is j-independent (folded out of the inner loop).
//
//  idcg: exact counting-rank over an 8192-bin histogram of y in [0,1);
//  in-bin ties use the bin-mean y across their consecutive exact ranks
//  (tied y's differ by < 2^-13; error ~1e-7 relative).
//
//  loss = (sum(y) < 1) ? 0 : 1 - dcg/(idcg + 1e-8)
//
//  Replay contract: histograms are __device__ globals zero-initialized at
//  load; k_final re-zeroes them after consuming, so every graph replay
//  starts from zero without a dedicated zeroing kernel.

#define TPB_H   256
#define TPB_R   64
#define TPB_F   1024
#define G       1024
#define YB      8192
#define YPT     (YB / TPB_F)        // 8 y-bins per k_final thread
#define MAXRB   512

#define S_LO   (-6.0f)
#define S_HI   ( 6.0f)

__device__ float g_SH[2 * G];       // interleaved {H, S1} per s-bin (atomics)
__device__ float g_YC[YB];          // y-bin counts (exact integers)
__device__ float g_YS[YB];          // y-bin value sums
__device__ float g_dcgP[MAXRB];     // per-block DCG partials

__device__ __forceinline__ float tanh_approx(float x) {
    float r;
    asm("tanh.approx.f32 %0, %1;" : "=f"(r) : "f"(x));
    return r;
}

// ---------------------------------------------------------------------------
// K1: build both histograms.
// ---------------------------------------------------------------------------
__global__ void __launch_bounds__(TPB_H)
k_hist(const float* __restrict__ s, const float* __restrict__ y, int n)
{
    const int j = blockIdx.x * TPB_H + threadIdx.x;
    if (j >= n) return;

    const float h     = (S_HI - S_LO) / (float)G;
    const float inv_h = (float)G / (S_HI - S_LO);

    const float sv = s[j];
    int g = (int)((sv - S_LO) * inv_h);
    g = max(0, min(G - 1, g));
    const float c = S_LO + ((float)g + 0.5f) * h;
    atomicAdd(&g_SH[2 * g],     1.0f);
    atomicAdd(&g_SH[2 * g + 1], sv - c);

    const float yv = y[j];
    int q = (int)(yv * (float)YB);
    q = max(0, min(YB - 1, q));
    atomicAdd(&g_YC[q], 1.0f);
    atomicAdd(&g_YS[q], yv);
}

// ---------------------------------------------------------------------------
// K2: per-j sigmoid-sum via the binned convolution + per-block DCG partial.
// ---------------------------------------------------------------------------
__global__ void __launch_bounds__(TPB_R)
k_rank_dcg(const float* __restrict__ s, const float* __restrict__ y, int n)
{
    __shared__ float2 sh[G];        // {a1, a2} per bin
    __shared__ float  red[TPB_R];

    const int j = blockIdx.x * TPB_R + threadIdx.x;

    // Stage + transform: a1 = 0.5*H, a2 = 0.25*S1; accumulate a0 partial.
    float a0loc = 0.0f;
    for (int t = threadIdx.x; t < G; t += TPB_R) {
        const float2 hs = reinterpret_cast<const float2*>(g_SH)[t];
        const float a1 = 0.5f  * hs.x;
        const float a2 = 0.25f * hs.y;
        sh[t] = make_float2(a1, a2);
        a0loc += a1 - a2;           // 0.5H - 0.25S1
    }
    red[threadIdx.x] = a0loc;
    __syncthreads();
    #pragma unroll
    for (int off = TPB_R / 2; off > 0; off >>= 1) {
        if (threadIdx.x < off) red[threadIdx.x] += red[threadIdx.x + off];
        __syncthreads();
    }
    const float a0tot = red[0];
    __syncthreads();

    const float h  = (S_HI - S_LO) / (float)G;
    const float hh = 0.5f * h;
    const float sv = (j < n) ? s[j] : 0.0f;
    float u = 0.5f * sv - 0.5f * (S_LO + 0.5f * h);   // 0.5*(s_j - c_0)

    float acc = 0.0f;
    #pragma unroll 8
    for (int t = 0; t < G; t++) {
        const float th = tanh_approx(u);
        u -= hh;
        const float2 a = sh[t];
        acc = fmaf(th, fmaf(th, a.y, a.x), acc);
    }

    float dcg = 0.0f;
    if (j < n) {
        const float rank = 1.0f + a0tot + acc;
        dcg = __fdividef(y[j], __log2f(rank + 1.0f));
    }

    red[threadIdx.x] = dcg;
    __syncthreads();
    #pragma unroll
    for (int off = TPB_R / 2; off > 0; off >>= 1) {
        if (threadIdx.x < off) red[threadIdx.x] += red[threadIdx.x + off];
        __syncthreads();
    }
    if (threadIdx.x == 0) g_dcgP[blockIdx.x] = red[0];
}

// ---------------------------------------------------------------------------
// K3: single block — y-side exact-rank IDCG, DCG sum, loss, histogram reset.
// ---------------------------------------------------------------------------
__global__ void __launch_bounds__(TPB_F)
k_final(float* __restrict__ out, int rblocks)
{
    __shared__ float sc[TPB_F];
    __shared__ float r1[TPB_F], r2[TPB_F], r3[TPB_F];

    const int t = threadIdx.x;

    // Per-thread bins [YPT*t, YPT*t+YPT): counts, value sums.
    float cnt[YPT];
    float ysum = 0.0f, Tt = 0.0f;
    #pragma unroll
    for (int b = 0; b < YPT; b++) {
        cnt[b] = g_YC[YPT * t + b];
        Tt    += cnt[b];
        ysum  += g_YS[YPT * t + b];
    }

    // Inclusive suffix scan of per-thread totals (Hillis-Steele).
    sc[t] = Tt;
    __syncthreads();
    #pragma unroll
    for (int off = 1; off < TPB_F; off <<= 1) {
        const float v = (t + off < TPB_F) ? sc[t + off] : 0.0f;
        __syncthreads();
        sc[t] += v;
        __syncthreads();
    }
    float above = sc[t] - Tt;       // elements in strictly-higher threads

    // Walk own bins from highest y downward, exact consecutive ranks.
    float idg = 0.0f;
    #pragma unroll
    for (int b = YPT - 1; b >= 0; b--) {
        const int c = (int)cnt[b];
        if (c > 0) {
            const float ybar = __fdividef(g_YS[YPT * t + b], (float)c);
            for (int k = 1; k <= c; k++) {
                const float rank = above + (float)k;
                idg += __fdividef(ybar, __log2f(rank + 1.0f));
            }
            above += (float)c;
        }
    }

    // Combined reductions: idcg, sum(y), dcg.
    float d = (t < rblocks) ? g_dcgP[t] : 0.0f;
    r1[t] = idg; r2[t] = ysum; r3[t] = d;
    __syncthreads();
    #pragma unroll
    for (int off = TPB_F / 2; off > 0; off >>= 1) {
        if (t < off) {
            r1[t] += r1[t + off];
            r2[t] += r2[t + off];
            r3[t] += r3[t + off];
        }
        __syncthreads();
    }
    if (t == 0) {
        const float ndcg = r3[0] / (r1[0] + 1e-8f);
        const float loss = 1.0f - ndcg;
        out[0] = (r2[0] < 1.0f) ? 0.0f : loss;
    }

    // Reset histograms for the next graph replay.
    for (int i = t; i < 2 * G; i += TPB_F) g_SH[i] = 0.0f;
    #pragma unroll
    for (int b = 0; b < YPT; b++) {
        g_YC[YPT * t + b] = 0.0f;
        g_YS[YPT * t + b] = 0.0f;
    }
}

// ---------------------------------------------------------------------------
extern "C" void kernel_launch(void* const* d_in, const int* in_sizes, int n_in,
                              void* d_out, int out_size)
{
    const float* s = (const float*)d_in[0];   // logits
    const float* y = (const float*)d_in[1];   // targets
    float* out = (float*)d_out;
    const int n = in_sizes[0];

    const int hblocks = (n + TPB_H - 1) / TPB_H;
    const int rblocks = (n + TPB_R - 1) / TPB_R;

    k_hist<<<hblocks, TPB_H>>>(s, y, n);
    k_rank_dcg<<<rblocks, TPB_R>>>(s, y, n);
    k_final<<<1, TPB_F>>>(out, rblocks);
}